// round 14
// baseline (speedup 1.0000x reference)
#include <cuda_runtime.h>
#include <cstdint>

#define SEQ 128
#define BATCH 256
#define N_IN 1024
#define N_ST 256

// ---------------- static device scratch (no allocations allowed) ----------------
__device__ uint32_t g_inp[SEQ * BATCH * 8];     // packed input bits: [t][b][8 words]
__device__ uint32_t g_memA[N_IN * 2048];        // packed input-layer RAM: [n][2048 words]
__device__ uint32_t g_memB[N_ST * 2048];        // packed state-layer RAM
__device__ uint32_t g_connA[N_IN * 16];         // (shift<<16) | (row_word_offset)
__device__ uint32_t g_connB[N_ST * 16];

#define NW_INP  (SEQ * BATCH * 8)       // 262144
#define NW_MEMA (N_IN * 2048)           // 2097152
#define NW_MEMB (N_ST * 2048)           // 524288
#define NW_ALL  (NW_INP + NW_MEMA + NW_MEMB)   // 2883584 words

// Ballot-based pack: warp g handles packed word g; lane l reads float 32*g+l
// (fully coalesced, 1 line per warp-load), ballot assembles the word.
__global__ void pack_all_kernel(const float* __restrict__ inp,
                                const float* __restrict__ memA,
                                const float* __restrict__ memB,
                                uint32_t* __restrict__ d_inp,
                                uint32_t* __restrict__ d_memA,
                                uint32_t* __restrict__ d_memB) {
    int g = (blockIdx.x * blockDim.x + threadIdx.x) >> 5;   // global warp id
    int lane = threadIdx.x & 31;
    if (g >= NW_ALL) return;
    const float* src; uint32_t* dst; int j;
    if (g < NW_INP)                 { src = inp;  dst = d_inp;  j = g; }
    else if (g < NW_INP + NW_MEMA)  { src = memA; dst = d_memA; j = g - NW_INP; }
    else                            { src = memB; dst = d_memB; j = g - NW_INP - NW_MEMA; }
    float f = __ldcs(&src[(size_t)j * 32 + lane]);          // streaming, no reuse
    uint32_t word = __ballot_sync(0xffffffffu, f != 0.0f);
    if (lane == 0) dst[j] = word;
}

// Unified layout U (48 rows x 32 lanes): rows 0-7 inp, 8-15 state, 16-47 io.
// connA p in [0,512): row = p>>5.  connB p in [0,1280): io -> 16+(p>>5),
// state (p>=1024) -> (p>>5)-24.  Encoded as (shift<<16) | row*32.
__global__ void pack_conn_all_kernel(const int* __restrict__ connA,
                                     const int* __restrict__ connB,
                                     uint32_t* __restrict__ dA,
                                     uint32_t* __restrict__ dB) {
    int i = blockIdx.x * blockDim.x + threadIdx.x;
    if (i < N_IN * 16) {
        uint32_t v = (uint32_t)connA[i];
        dA[i] = ((v & 31u) << 16) | ((v >> 5) * 32u);
    } else if (i < N_IN * 16 + N_ST * 16) {
        int j = i - N_IN * 16;
        uint32_t v = (uint32_t)connB[j];
        uint32_t row = (v < 1024u) ? (16u + (v >> 5)) : ((v >> 5) - 24u);
        dB[j] = ((v & 31u) << 16) | (row * 32u);
    }
}

// ---------------- main recurrent kernel (R10 body — proven fastest) ----------------
__device__ __forceinline__ uint32_t gstep(uint32_t a, uint32_t c,
                                          const uint32_t* __restrict__ rep, int lane) {
    uint32_t w = rep[(c & 0xffffu) + lane];
    return (a + a) | ((w >> (c >> 16)) & 1u);
}

__device__ __forceinline__ uint32_t gather16(const uint32_t* __restrict__ cw,
                                             const uint32_t* __restrict__ rep, int lane) {
    uint32_t a = 0;
#pragma unroll
    for (int k = 15; k >= 0; --k) a = gstep(a, cw[k], rep, lane);
    return a;
}

__global__ __launch_bounds__(256, 2)
void ram_main(const float* __restrict__ init_state, float* __restrict__ out) {
    // Ping-ponged lane-replicated bit vectors (bank == lane -> conflict-free).
    __shared__ uint32_t U[2][48 * 32];

    const int tid  = threadIdx.x;
    const int lane = tid & 31;
    const int w    = tid >> 5;          // warp 0..7
    const int b    = blockIdx.x;        // one batch per block

    // Hoist loop-invariant connections into registers (64 + 16 words).
    uint32_t cA[64], cB[16];
#pragma unroll
    for (int gi = 0; gi < 4; ++gi) {
        int n = (w * 4 + gi) * 32 + lane;
#pragma unroll
        for (int k = 0; k < 16; ++k) cA[gi * 16 + k] = g_connA[n * 16 + k];
    }
    {
        int m = w * 32 + lane;
#pragma unroll
        for (int k = 0; k < 16; ++k) cB[k] = g_connB[m * 16 + k];
    }

    // init state words into copy 0 (used by step 0)
    {
        float f = init_state[b * N_ST + w * 32 + lane];
        uint32_t word = __ballot_sync(0xffffffffu, f != 0.0f);
        U[0][(8 + w) * 32 + lane] = word;
    }

    for (int t = 0; t < SEQ; ++t) {
        uint32_t* cur = U[t & 1];
        uint32_t* nxt = U[(t + 1) & 1];

        // packed input bits for this step (broadcast load, replicated to lanes)
        cur[w * 32 + lane] = g_inp[((size_t)t * BATCH + b) * 8 + w];
        __syncthreads();   // input + previously installed state visible

        // ---- phase A: 1024 neurons; warp w handles groups w*4 .. w*4+3 ----
        float* outrow = out + ((size_t)t * BATCH + b) * N_IN;
        uint32_t acc[4], tw[4];
#pragma unroll
        for (int gi = 0; gi < 4; ++gi)
            acc[gi] = gather16(&cA[gi * 16], cur, lane);
#pragma unroll
        for (int gi = 0; gi < 4; ++gi) {   // 4 table lookups in flight (L2)
            int n = (w * 4 + gi) * 32 + lane;
            tw[gi] = __ldcg(&g_memA[n * 2048 + (acc[gi] >> 5)]);
        }
#pragma unroll
        for (int gi = 0; gi < 4; ++gi) {
            int g = w * 4 + gi;
            uint32_t bit = (tw[gi] >> (acc[gi] & 31u)) & 1u;
            uint32_t iow = __ballot_sync(0xffffffffu, bit != 0u);
            cur[(16 + g) * 32 + lane] = iow;          // replicate io word
            outrow[g * 32 + lane] = (float)bit;       // coalesced 128B store
        }
        __syncthreads();   // io words visible

        // ---- phase B: 256 neurons; warp w handles neurons w*32 .. w*32+31 ----
        int m = w * 32 + lane;
        uint32_t a   = gather16(cB, cur, lane);
        uint32_t twb = __ldcg(&g_memB[m * 2048 + (a >> 5)]);
        uint32_t bit = (twb >> (a & 31u)) & 1u;
        uint32_t sw2 = __ballot_sync(0xffffffffu, bit != 0u);

        if (t == SEQ - 1) {
            out[(size_t)SEQ * BATCH * N_IN + b * N_ST + m] = (float)bit;
        }
        // Install next state into the OTHER copy: no barrier needed here;
        // readers sync on the next iteration's top __syncthreads().
        nxt[(8 + w) * 32 + lane] = sw2;
    }
}

extern "C" void kernel_launch(void* const* d_in, const int* in_sizes, int n_in,
                              void* d_out, int out_size) {
    const float* inp        = (const float*)d_in[0];  // [128,256,256] bool->f32
    const float* init_state = (const float*)d_in[1];  // [256,256] bool->f32
    const int*   connA      = (const int*)d_in[2];    // [1024,16] int32
    const float* memA       = (const float*)d_in[3];  // [1024,65536] bool->f32
    const int*   connB      = (const int*)d_in[4];    // [256,16] int32
    const float* memB       = (const float*)d_in[5];  // [256,65536] bool->f32
    float* out = (float*)d_out;
    (void)in_sizes; (void)n_in; (void)out_size;

    uint32_t *p_inp, *p_memA, *p_memB, *p_connA, *p_connB;
    cudaGetSymbolAddress((void**)&p_inp,   g_inp);
    cudaGetSymbolAddress((void**)&p_memA,  g_memA);
    cudaGetSymbolAddress((void**)&p_memB,  g_memB);
    cudaGetSymbolAddress((void**)&p_connA, g_connA);
    cudaGetSymbolAddress((void**)&p_connB, g_connB);

    // precompute: ballot-based bit-pack (1 warp per word, coalesced) + conn decode
    {
        long long nthreads = (long long)NW_ALL * 32;
        pack_all_kernel<<<(int)((nthreads + 255) / 256), 256>>>(
            inp, memA, memB, p_inp, p_memA, p_memB);
    }
    pack_conn_all_kernel<<<((N_IN + N_ST) * 16 + 255) / 256, 256>>>(
        connA, connB, p_connA, p_connB);

    // main recurrence: 256 blocks, one independent batch chain each
    ram_main<<<BATCH, 256>>>(init_state, out);
}

// round 15
// speedup vs baseline: 1.4413x; 1.4413x over previous
#include <cuda_runtime.h>
#include <cstdint>

#define SEQ 128
#define BATCH 256
#define N_IN 1024
#define N_ST 256

// ---------------- static device scratch (no allocations allowed) ----------------
__device__ uint32_t g_inp[SEQ * BATCH * 8];     // packed input bits: [t][b][8 words]
__device__ uint32_t g_memA[N_IN * 2048];        // packed input-layer RAM: [n][2048 words]
__device__ uint32_t g_memB[N_ST * 2048];        // packed state-layer RAM
__device__ uint32_t g_connA[N_IN * 16];         // (shift<<16) | (row_word_offset)
__device__ uint32_t g_connB[N_ST * 16];

#define NW_INP  (SEQ * BATCH * 8)       // 262144
#define NW_MEMA (N_IN * 2048)           // 2097152
#define NW_MEMB (N_ST * 2048)           // 524288
#define NW_ALL  (NW_INP + NW_MEMA + NW_MEMB)   // 2883584 words (all /32)
#define NTILES  (NW_ALL / 32)                  // 90112 warp-tiles

// Amortized ballot pack: warp handles a 4KB tile = 32 packed words.
// Iter i: lane l reads float (tile*32+i)*32 + l  (fully coalesced, 1 line);
// ballot assembles word i; lane i retains it; one coalesced 128B store.
__global__ void pack_all_kernel(const float* __restrict__ inp,
                                const float* __restrict__ memA,
                                const float* __restrict__ memB,
                                uint32_t* __restrict__ d_inp,
                                uint32_t* __restrict__ d_memA,
                                uint32_t* __restrict__ d_memB) {
    int tile = (blockIdx.x * blockDim.x + threadIdx.x) >> 5;  // global warp id
    int lane = threadIdx.x & 31;
    if (tile >= NTILES) return;

    int w0 = tile * 32;                       // first packed-word index of tile
    const float* src; uint32_t* dst; int j0;
    if (w0 < NW_INP)                 { src = inp;  dst = d_inp;  j0 = w0; }
    else if (w0 < NW_INP + NW_MEMA)  { src = memA; dst = d_memA; j0 = w0 - NW_INP; }
    else                             { src = memB; dst = d_memB; j0 = w0 - NW_INP - NW_MEMA; }

    const float* p = src + (size_t)j0 * 32 + lane;
    uint32_t myword = 0;
#pragma unroll
    for (int i = 0; i < 32; ++i) {
        float f = __ldcs(p + (size_t)i * 32);            // streaming, coalesced
        uint32_t word = __ballot_sync(0xffffffffu, f != 0.0f);
        if (i == lane) myword = word;                     // SEL, no branch
    }
    dst[j0 + lane] = myword;                              // coalesced 128B store
}

// Unified layout U (48 rows x 32 lanes): rows 0-7 inp, 8-15 state, 16-47 io.
// connA p in [0,512): row = p>>5.  connB p in [0,1280): io -> 16+(p>>5),
// state (p>=1024) -> (p>>5)-24.  Encoded as (shift<<16) | row*32.
__global__ void pack_conn_all_kernel(const int* __restrict__ connA,
                                     const int* __restrict__ connB,
                                     uint32_t* __restrict__ dA,
                                     uint32_t* __restrict__ dB) {
    int i = blockIdx.x * blockDim.x + threadIdx.x;
    if (i < N_IN * 16) {
        uint32_t v = (uint32_t)connA[i];
        dA[i] = ((v & 31u) << 16) | ((v >> 5) * 32u);
    } else if (i < N_IN * 16 + N_ST * 16) {
        int j = i - N_IN * 16;
        uint32_t v = (uint32_t)connB[j];
        uint32_t row = (v < 1024u) ? (16u + (v >> 5)) : ((v >> 5) - 24u);
        dB[j] = ((v & 31u) << 16) | (row * 32u);
    }
}

// ---------------- main recurrent kernel (R10 body — proven fastest) ----------------
__device__ __forceinline__ uint32_t gstep(uint32_t a, uint32_t c,
                                          const uint32_t* __restrict__ rep, int lane) {
    uint32_t w = rep[(c & 0xffffu) + lane];
    return (a + a) | ((w >> (c >> 16)) & 1u);
}

__device__ __forceinline__ uint32_t gather16(const uint32_t* __restrict__ cw,
                                             const uint32_t* __restrict__ rep, int lane) {
    uint32_t a = 0;
#pragma unroll
    for (int k = 15; k >= 0; --k) a = gstep(a, cw[k], rep, lane);
    return a;
}

__global__ __launch_bounds__(256, 2)
void ram_main(const float* __restrict__ init_state, float* __restrict__ out) {
    // Ping-ponged lane-replicated bit vectors (bank == lane -> conflict-free).
    __shared__ uint32_t U[2][48 * 32];

    const int tid  = threadIdx.x;
    const int lane = tid & 31;
    const int w    = tid >> 5;          // warp 0..7
    const int b    = blockIdx.x;        // one batch per block

    // Hoist loop-invariant connections into registers (64 + 16 words).
    uint32_t cA[64], cB[16];
#pragma unroll
    for (int gi = 0; gi < 4; ++gi) {
        int n = (w * 4 + gi) * 32 + lane;
#pragma unroll
        for (int k = 0; k < 16; ++k) cA[gi * 16 + k] = g_connA[n * 16 + k];
    }
    {
        int m = w * 32 + lane;
#pragma unroll
        for (int k = 0; k < 16; ++k) cB[k] = g_connB[m * 16 + k];
    }

    // init state words into copy 0 (used by step 0)
    {
        float f = init_state[b * N_ST + w * 32 + lane];
        uint32_t word = __ballot_sync(0xffffffffu, f != 0.0f);
        U[0][(8 + w) * 32 + lane] = word;
    }

    for (int t = 0; t < SEQ; ++t) {
        uint32_t* cur = U[t & 1];
        uint32_t* nxt = U[(t + 1) & 1];

        // packed input bits for this step (broadcast load, replicated to lanes)
        cur[w * 32 + lane] = g_inp[((size_t)t * BATCH + b) * 8 + w];
        __syncthreads();   // input + previously installed state visible

        // ---- phase A: 1024 neurons; warp w handles groups w*4 .. w*4+3 ----
        float* outrow = out + ((size_t)t * BATCH + b) * N_IN;
        uint32_t acc[4], tw[4];
#pragma unroll
        for (int gi = 0; gi < 4; ++gi)
            acc[gi] = gather16(&cA[gi * 16], cur, lane);
#pragma unroll
        for (int gi = 0; gi < 4; ++gi) {   // 4 table lookups in flight (L2)
            int n = (w * 4 + gi) * 32 + lane;
            tw[gi] = __ldcg(&g_memA[n * 2048 + (acc[gi] >> 5)]);
        }
#pragma unroll
        for (int gi = 0; gi < 4; ++gi) {
            int g = w * 4 + gi;
            uint32_t bit = (tw[gi] >> (acc[gi] & 31u)) & 1u;
            uint32_t iow = __ballot_sync(0xffffffffu, bit != 0u);
            cur[(16 + g) * 32 + lane] = iow;          // replicate io word
            outrow[g * 32 + lane] = (float)bit;       // coalesced 128B store
        }
        __syncthreads();   // io words visible

        // ---- phase B: 256 neurons; warp w handles neurons w*32 .. w*32+31 ----
        int m = w * 32 + lane;
        uint32_t a   = gather16(cB, cur, lane);
        uint32_t twb = __ldcg(&g_memB[m * 2048 + (a >> 5)]);
        uint32_t bit = (twb >> (a & 31u)) & 1u;
        uint32_t sw2 = __ballot_sync(0xffffffffu, bit != 0u);

        if (t == SEQ - 1) {
            out[(size_t)SEQ * BATCH * N_IN + b * N_ST + m] = (float)bit;
        }
        // Install next state into the OTHER copy: no barrier needed here;
        // readers sync on the next iteration's top __syncthreads().
        nxt[(8 + w) * 32 + lane] = sw2;
    }
}

extern "C" void kernel_launch(void* const* d_in, const int* in_sizes, int n_in,
                              void* d_out, int out_size) {
    const float* inp        = (const float*)d_in[0];  // [128,256,256] bool->f32
    const float* init_state = (const float*)d_in[1];  // [256,256] bool->f32
    const int*   connA      = (const int*)d_in[2];    // [1024,16] int32
    const float* memA       = (const float*)d_in[3];  // [1024,65536] bool->f32
    const int*   connB      = (const int*)d_in[4];    // [256,16] int32
    const float* memB       = (const float*)d_in[5];  // [256,65536] bool->f32
    float* out = (float*)d_out;
    (void)in_sizes; (void)n_in; (void)out_size;

    uint32_t *p_inp, *p_memA, *p_memB, *p_connA, *p_connB;
    cudaGetSymbolAddress((void**)&p_inp,   g_inp);
    cudaGetSymbolAddress((void**)&p_memA,  g_memA);
    cudaGetSymbolAddress((void**)&p_memB,  g_memB);
    cudaGetSymbolAddress((void**)&p_connA, g_connA);
    cudaGetSymbolAddress((void**)&p_connB, g_connB);

    // precompute: warp-tile ballot pack (coalesced, amortized) + conn decode
    {
        long long nthreads = (long long)NTILES * 32;   // 2883584 threads
        pack_all_kernel<<<(int)((nthreads + 255) / 256), 256>>>(
            inp, memA, memB, p_inp, p_memA, p_memB);
    }
    pack_conn_all_kernel<<<((N_IN + N_ST) * 16 + 255) / 256, 256>>>(
        connA, connB, p_connA, p_connB);

    // main recurrence: 256 blocks, one independent batch chain each
    ram_main<<<BATCH, 256>>>(init_state, out);
}

// round 16
// speedup vs baseline: 1.4494x; 1.0056x over previous
#include <cuda_runtime.h>
#include <cstdint>

#define SEQ 128
#define BATCH 256
#define N_IN 1024
#define N_ST 256

// ---------------- static device scratch (no allocations allowed) ----------------
__device__ uint32_t g_inp[SEQ * BATCH * 8];     // packed input bits: [t][b][8 words]
__device__ uint32_t g_memA[N_IN * 2048];        // packed input-layer RAM: [n][2048 words]
__device__ uint32_t g_memB[N_ST * 2048];        // packed state-layer RAM
__device__ uint32_t g_connA[N_IN * 16];         // (shift<<16) | (row_word_offset)
__device__ uint32_t g_connB[N_ST * 16];

#define NW_INP  (SEQ * BATCH * 8)       // 262144
#define NW_MEMA (N_IN * 2048)           // 2097152
#define NW_MEMB (N_ST * 2048)           // 524288
#define NW_ALL  (NW_INP + NW_MEMA + NW_MEMB)   // 2883584 words (all /32)
#define NTILES  (NW_ALL / 32)                  // 90112 warp-tiles

// Amortized ballot pack: warp handles a 4KB tile = 32 packed words.
// Iter i: lane l reads float (tile*32+i)*32 + l  (fully coalesced, 1 line);
// ballot assembles word i; lane i retains it; one coalesced 128B store.
__global__ void pack_all_kernel(const float* __restrict__ inp,
                                const float* __restrict__ memA,
                                const float* __restrict__ memB,
                                uint32_t* __restrict__ d_inp,
                                uint32_t* __restrict__ d_memA,
                                uint32_t* __restrict__ d_memB) {
    int tile = (blockIdx.x * blockDim.x + threadIdx.x) >> 5;  // global warp id
    int lane = threadIdx.x & 31;
    if (tile >= NTILES) return;

    int w0 = tile * 32;                       // first packed-word index of tile
    const float* src; uint32_t* dst; int j0;
    if (w0 < NW_INP)                 { src = inp;  dst = d_inp;  j0 = w0; }
    else if (w0 < NW_INP + NW_MEMA)  { src = memA; dst = d_memA; j0 = w0 - NW_INP; }
    else                             { src = memB; dst = d_memB; j0 = w0 - NW_INP - NW_MEMA; }

    const float* p = src + (size_t)j0 * 32 + lane;
    uint32_t myword = 0;
#pragma unroll
    for (int i = 0; i < 32; ++i) {
        float f = __ldcs(p + (size_t)i * 32);            // streaming, coalesced
        uint32_t word = __ballot_sync(0xffffffffu, f != 0.0f);
        if (i == lane) myword = word;                     // SEL, no branch
    }
    dst[j0 + lane] = myword;                              // coalesced 128B store
}

// Unified layout U (48 rows x 32 lanes): rows 0-7 inp, 8-15 state, 16-47 io.
// connA p in [0,512): row = p>>5.  connB p in [0,1280): io -> 16+(p>>5),
// state (p>=1024) -> (p>>5)-24.  Encoded as (shift<<16) | row*32.
__global__ void pack_conn_all_kernel(const int* __restrict__ connA,
                                     const int* __restrict__ connB,
                                     uint32_t* __restrict__ dA,
                                     uint32_t* __restrict__ dB) {
    int i = blockIdx.x * blockDim.x + threadIdx.x;
    if (i < N_IN * 16) {
        uint32_t v = (uint32_t)connA[i];
        dA[i] = ((v & 31u) << 16) | ((v >> 5) * 32u);
    } else if (i < N_IN * 16 + N_ST * 16) {
        int j = i - N_IN * 16;
        uint32_t v = (uint32_t)connB[j];
        uint32_t row = (v < 1024u) ? (16u + (v >> 5)) : ((v >> 5) - 24u);
        dB[j] = ((v & 31u) << 16) | (row * 32u);
    }
}

// ---------------- main recurrent kernel (R10 body — proven fastest) ----------------
__device__ __forceinline__ uint32_t gstep(uint32_t a, uint32_t c,
                                          const uint32_t* __restrict__ rep, int lane) {
    uint32_t w = rep[(c & 0xffffu) + lane];
    return (a + a) | ((w >> (c >> 16)) & 1u);
}

__device__ __forceinline__ uint32_t gather16(const uint32_t* __restrict__ cw,
                                             const uint32_t* __restrict__ rep, int lane) {
    uint32_t a = 0;
#pragma unroll
    for (int k = 15; k >= 0; --k) a = gstep(a, cw[k], rep, lane);
    return a;
}

__global__ __launch_bounds__(256, 2)
void ram_main(const float* __restrict__ init_state, float* __restrict__ out) {
    // Ping-ponged lane-replicated bit vectors (bank == lane -> conflict-free).
    __shared__ uint32_t U[2][48 * 32];

    const int tid  = threadIdx.x;
    const int lane = tid & 31;
    const int w    = tid >> 5;          // warp 0..7
    const int b    = blockIdx.x;        // one batch per block

    // Hoist loop-invariant connections into registers (64 + 16 words).
    uint32_t cA[64], cB[16];
#pragma unroll
    for (int gi = 0; gi < 4; ++gi) {
        int n = (w * 4 + gi) * 32 + lane;
#pragma unroll
        for (int k = 0; k < 16; ++k) cA[gi * 16 + k] = g_connA[n * 16 + k];
    }
    {
        int m = w * 32 + lane;
#pragma unroll
        for (int k = 0; k < 16; ++k) cB[k] = g_connB[m * 16 + k];
    }

    // init state words into copy 0 (used by step 0)
    {
        float f = init_state[b * N_ST + w * 32 + lane];
        uint32_t word = __ballot_sync(0xffffffffu, f != 0.0f);
        U[0][(8 + w) * 32 + lane] = word;
    }

    for (int t = 0; t < SEQ; ++t) {
        uint32_t* cur = U[t & 1];
        uint32_t* nxt = U[(t + 1) & 1];

        // packed input bits for this step (broadcast load, replicated to lanes)
        cur[w * 32 + lane] = g_inp[((size_t)t * BATCH + b) * 8 + w];
        __syncthreads();   // input + previously installed state visible

        // ---- phase A: 1024 neurons; warp w handles groups w*4 .. w*4+3 ----
        float* outrow = out + ((size_t)t * BATCH + b) * N_IN;
        uint32_t acc[4], tw[4];
#pragma unroll
        for (int gi = 0; gi < 4; ++gi)
            acc[gi] = gather16(&cA[gi * 16], cur, lane);
#pragma unroll
        for (int gi = 0; gi < 4; ++gi) {   // 4 table lookups in flight (L2)
            int n = (w * 4 + gi) * 32 + lane;
            tw[gi] = __ldcg(&g_memA[n * 2048 + (acc[gi] >> 5)]);
        }
#pragma unroll
        for (int gi = 0; gi < 4; ++gi) {
            int g = w * 4 + gi;
            uint32_t bit = (tw[gi] >> (acc[gi] & 31u)) & 1u;
            uint32_t iow = __ballot_sync(0xffffffffu, bit != 0u);
            cur[(16 + g) * 32 + lane] = iow;          // replicate io word
            outrow[g * 32 + lane] = (float)bit;       // coalesced 128B store
        }
        __syncthreads();   // io words visible

        // ---- phase B: 256 neurons; warp w handles neurons w*32 .. w*32+31 ----
        int m = w * 32 + lane;
        uint32_t a   = gather16(cB, cur, lane);
        uint32_t twb = __ldcg(&g_memB[m * 2048 + (a >> 5)]);
        uint32_t bit = (twb >> (a & 31u)) & 1u;
        uint32_t sw2 = __ballot_sync(0xffffffffu, bit != 0u);

        if (t == SEQ - 1) {
            out[(size_t)SEQ * BATCH * N_IN + b * N_ST + m] = (float)bit;
        }
        // Install next state into the OTHER copy: no barrier needed here;
        // readers sync on the next iteration's top __syncthreads().
        nxt[(8 + w) * 32 + lane] = sw2;
    }
}

extern "C" void kernel_launch(void* const* d_in, const int* in_sizes, int n_in,
                              void* d_out, int out_size) {
    const float* inp        = (const float*)d_in[0];  // [128,256,256] bool->f32
    const float* init_state = (const float*)d_in[1];  // [256,256] bool->f32
    const int*   connA      = (const int*)d_in[2];    // [1024,16] int32
    const float* memA       = (const float*)d_in[3];  // [1024,65536] bool->f32
    const int*   connB      = (const int*)d_in[4];    // [256,16] int32
    const float* memB       = (const float*)d_in[5];  // [256,65536] bool->f32
    float* out = (float*)d_out;
    (void)in_sizes; (void)n_in; (void)out_size;

    uint32_t *p_inp, *p_memA, *p_memB, *p_connA, *p_connB;
    cudaGetSymbolAddress((void**)&p_inp,   g_inp);
    cudaGetSymbolAddress((void**)&p_memA,  g_memA);
    cudaGetSymbolAddress((void**)&p_memB,  g_memB);
    cudaGetSymbolAddress((void**)&p_connA, g_connA);
    cudaGetSymbolAddress((void**)&p_connB, g_connB);

    // precompute: warp-tile ballot pack (coalesced, amortized) + conn decode
    {
        long long nthreads = (long long)NTILES * 32;   // 2883584 threads
        pack_all_kernel<<<(int)((nthreads + 255) / 256), 256>>>(
            inp, memA, memB, p_inp, p_memA, p_memB);
    }
    pack_conn_all_kernel<<<((N_IN + N_ST) * 16 + 255) / 256, 256>>>(
        connA, connB, p_connA, p_connB);

    // main recurrence: 256 blocks, one independent batch chain each
    ram_main<<<BATCH, 256>>>(init_state, out);
}